// round 4
// baseline (speedup 1.0000x reference)
#include <cuda_runtime.h>
#include <cuda_bf16.h>

#define OUT_UNITS 128
#define MAX_ROWS  16384
#define WARPS_PER_BLOCK 8

// ---------------------------------------------------------------------------
// Scratch (device globals — no allocation allowed in kernel_launch)
// ---------------------------------------------------------------------------
__device__ int g_is64;                       // 1 if rows/cols are int64, 0 if int32
__device__ int g_row_start[MAX_ROWS + 1];    // CSR-style row offsets

// ---------------------------------------------------------------------------
// Dtype probe: rows sorted ascending over [0, 16384). If int64 (LE), every odd
// 32-bit word is a zero high-half. If int32, odd words near n/4, n/2, 3n/4 are
// sorted row ids ~4096/8192/12288. Probed indices odd and < n: safe for both.
// ---------------------------------------------------------------------------
__device__ __forceinline__ int probe_is64(const int* __restrict__ rows32, int n) {
    int j1 = (n / 2) | 1;
    int j2 = (n / 4) | 1;
    int j3 = (int)(((long long)3 * n) / 4) | 1;
    int s = rows32[j1] | rows32[j2] | rows32[j3];
    return (s == 0) ? 1 : 0;
}

// ---------------------------------------------------------------------------
// Kernel 1: build row offsets from sorted COO rows (fused dtype detection).
// 4 elements per thread, vectorized int4 loads.
// ---------------------------------------------------------------------------
__global__ void build_offsets_kernel(const int* __restrict__ rows32, int nnz, int n_rows) {
    const int is64 = probe_is64(rows32, nnz);

    const int t  = blockIdx.x * blockDim.x + threadIdx.x;
    if (t == 0) g_is64 = is64;
    const int k0 = t * 4;
    if (k0 >= nnz) return;

    const int cnt = min(4, nnz - k0);
    int r[4];
    if (is64) {
        if (cnt == 4) {
            const int4 a = ((const int4*)rows32)[k0 / 2];
            const int4 b = ((const int4*)rows32)[k0 / 2 + 1];
            r[0] = a.x; r[1] = a.z; r[2] = b.x; r[3] = b.z;
        } else {
            for (int j = 0; j < cnt; j++) r[j] = rows32[2 * (k0 + j)];
        }
    } else {
        if (cnt == 4) {
            const int4 a = ((const int4*)rows32)[k0 / 4];
            r[0] = a.x; r[1] = a.y; r[2] = a.z; r[3] = a.w;
        } else {
            for (int j = 0; j < cnt; j++) r[j] = rows32[k0 + j];
        }
    }

    int rp = (k0 == 0) ? -1 : (is64 ? rows32[2 * (k0 - 1)] : rows32[k0 - 1]);
    for (int j = 0; j < cnt; j++) {
        const int rj = r[j];
        for (int x = rp + 1; x <= rj; x++) g_row_start[x] = k0 + j;
        rp = rj;
    }
    if (k0 + cnt == nnz) {
        for (int x = rp + 1; x <= n_rows; x++) g_row_start[x] = nnz;
    }
}

// ---------------------------------------------------------------------------
// Kernel 2: main SpMM. One WARP per output row; lane t owns output columns
// [4t, 4t+4) via float4.
//
// Warp-synchronous, no smem: each lane holds one (val, col) pair of the
// current 32-nnz chunk; pairs are broadcast with __shfl_sync. The NEXT chunk's
// (val, col) streaming loads are issued before the gather loop so their DRAM
// latency hides behind ~2000 cycles of W gathers. Chunks are padded with
// (v=0, c=0): dummy gathers hit the L1-resident col-0 row, keeping the
// batch-of-4 LDG.128 inner loop branch-free.
// ---------------------------------------------------------------------------
__global__ void __launch_bounds__(32 * WARPS_PER_BLOCK)
spmm_kernel(const float* __restrict__ values,
            const float* __restrict__ w,
            const int*   __restrict__ cols32,
            float*       __restrict__ out) {
    const int warp = threadIdx.x >> 5;
    const int lane = threadIdx.x & 31;
    const int r    = blockIdx.x * WARPS_PER_BLOCK + warp;
    const int is64 = g_is64;
    const unsigned FULL = 0xffffffffu;

    const int lo = g_row_start[r];
    const int hi = g_row_start[r + 1];

    float4 acc = make_float4(0.f, 0.f, 0.f, 0.f);
    const float4* __restrict__ w4 = (const float4*)w;   // w4[c*32 + lane]

    // Prime first chunk
    float v = 0.0f;
    int   c = 0;
    {
        const int k = lo + lane;
        if (k < hi) {
            v = values[k];
            c = is64 ? cols32[2 * k] : cols32[k];
        }
    }

    #pragma unroll 1
    for (int base = lo; base < hi; base += 32) {
        // Prefetch next chunk (overlaps the gather loop below)
        float vn = 0.0f;
        int   cn = 0;
        {
            const int kn = base + 32 + lane;
            if (kn < hi) {
                vn = values[kn];
                cn = is64 ? cols32[2 * kn] : cols32[kn];
            }
        }

        // Gather + accumulate, batches of 4 (4 LDG.128 in flight per warp)
        #pragma unroll 1
        for (int j = 0; j < 32; j += 4) {
            const float v0 = __shfl_sync(FULL, v, j + 0);
            const float v1 = __shfl_sync(FULL, v, j + 1);
            const float v2 = __shfl_sync(FULL, v, j + 2);
            const float v3 = __shfl_sync(FULL, v, j + 3);
            const int   c0 = __shfl_sync(FULL, c, j + 0);
            const int   c1 = __shfl_sync(FULL, c, j + 1);
            const int   c2 = __shfl_sync(FULL, c, j + 2);
            const int   c3 = __shfl_sync(FULL, c, j + 3);
            const float4 w0 = w4[(size_t)c0 * 32 + lane];
            const float4 w1 = w4[(size_t)c1 * 32 + lane];
            const float4 w2 = w4[(size_t)c2 * 32 + lane];
            const float4 w3 = w4[(size_t)c3 * 32 + lane];
            acc.x = fmaf(v0, w0.x, acc.x); acc.y = fmaf(v0, w0.y, acc.y);
            acc.z = fmaf(v0, w0.z, acc.z); acc.w = fmaf(v0, w0.w, acc.w);
            acc.x = fmaf(v1, w1.x, acc.x); acc.y = fmaf(v1, w1.y, acc.y);
            acc.z = fmaf(v1, w1.z, acc.z); acc.w = fmaf(v1, w1.w, acc.w);
            acc.x = fmaf(v2, w2.x, acc.x); acc.y = fmaf(v2, w2.y, acc.y);
            acc.z = fmaf(v2, w2.z, acc.z); acc.w = fmaf(v2, w2.w, acc.w);
            acc.x = fmaf(v3, w3.x, acc.x); acc.y = fmaf(v3, w3.y, acc.y);
            acc.z = fmaf(v3, w3.z, acc.z); acc.w = fmaf(v3, w3.w, acc.w);
        }

        v = vn;
        c = cn;
    }

    ((float4*)out)[(size_t)r * 32 + lane] = acc;
}

// ---------------------------------------------------------------------------
// Launch
// Inputs (metadata order): values f32[NNZ], w f32[8192*128],
//                          rows int{32,64}[NNZ], cols int{32,64}[NNZ], n_rows
// ---------------------------------------------------------------------------
extern "C" void kernel_launch(void* const* d_in, const int* in_sizes, int n_in,
                              void* d_out, int out_size) {
    const float* values = (const float*)d_in[0];
    const float* w      = (const float*)d_in[1];
    const int*   rows32 = (const int*)d_in[2];
    const int*   cols32 = (const int*)d_in[3];
    float*       out    = (float*)d_out;

    const int nnz    = in_sizes[0];
    const int n_rows = out_size / OUT_UNITS;

    const int bs = 256;
    const int nthreads = (nnz + 3) / 4;
    build_offsets_kernel<<<(nthreads + bs - 1) / bs, bs>>>(rows32, nnz, n_rows);

    spmm_kernel<<<n_rows / WARPS_PER_BLOCK, 32 * WARPS_PER_BLOCK>>>(values, w, cols32, out);
}

// round 5
// speedup vs baseline: 1.0528x; 1.0528x over previous
#include <cuda_runtime.h>
#include <cuda_bf16.h>

#define OUT_UNITS 128
#define MAX_ROWS  16384
#define WARPS_PER_BLOCK 8

// ---------------------------------------------------------------------------
// Scratch (device globals — no allocation allowed in kernel_launch)
// ---------------------------------------------------------------------------
__device__ int g_is64;                       // 1 if rows/cols are int64, 0 if int32
__device__ int g_row_start[MAX_ROWS + 1];    // CSR-style row offsets

// ---------------------------------------------------------------------------
// Dtype probe: rows sorted ascending over [0, 16384). If int64 (LE), every odd
// 32-bit word is a zero high-half. If int32, odd words near n/4, n/2, 3n/4 are
// sorted row ids ~4096/8192/12288. Probed indices odd and < n: safe for both.
// ---------------------------------------------------------------------------
__device__ __forceinline__ int probe_is64(const int* __restrict__ rows32, int n) {
    int j1 = (n / 2) | 1;
    int j2 = (n / 4) | 1;
    int j3 = (int)(((long long)3 * n) / 4) | 1;
    int s = rows32[j1] | rows32[j2] | rows32[j3];
    return (s == 0) ? 1 : 0;
}

// ---------------------------------------------------------------------------
// Kernel 1: build row offsets from sorted COO rows (fused dtype detection).
// 4 elements per thread, vectorized int4 loads.
// ---------------------------------------------------------------------------
__global__ void build_offsets_kernel(const int* __restrict__ rows32, int nnz, int n_rows) {
    const int is64 = probe_is64(rows32, nnz);

    const int t  = blockIdx.x * blockDim.x + threadIdx.x;
    if (t == 0) g_is64 = is64;
    const int k0 = t * 4;
    if (k0 >= nnz) return;

    const int cnt = min(4, nnz - k0);
    int r[4];
    if (is64) {
        if (cnt == 4) {
            const int4 a = ((const int4*)rows32)[k0 / 2];
            const int4 b = ((const int4*)rows32)[k0 / 2 + 1];
            r[0] = a.x; r[1] = a.z; r[2] = b.x; r[3] = b.z;
        } else {
            for (int j = 0; j < cnt; j++) r[j] = rows32[2 * (k0 + j)];
        }
    } else {
        if (cnt == 4) {
            const int4 a = ((const int4*)rows32)[k0 / 4];
            r[0] = a.x; r[1] = a.y; r[2] = a.z; r[3] = a.w;
        } else {
            for (int j = 0; j < cnt; j++) r[j] = rows32[k0 + j];
        }
    }

    int rp = (k0 == 0) ? -1 : (is64 ? rows32[2 * (k0 - 1)] : rows32[k0 - 1]);
    for (int j = 0; j < cnt; j++) {
        const int rj = r[j];
        for (int x = rp + 1; x <= rj; x++) g_row_start[x] = k0 + j;
        rp = rj;
    }
    if (k0 + cnt == nnz) {
        for (int x = rp + 1; x <= n_rows; x++) g_row_start[x] = nnz;
    }
}

// ---------------------------------------------------------------------------
// Kernel 2: main SpMM. One WARP per output row; lane t owns output columns
// [4t, 4t+4) via float4.
//
// Double-buffered smem staging: chunk i+1's (val, col) streaming loads are
// issued into registers before gathering chunk i, and written to the alternate
// buffer afterward — their DRAM latency hides under ~2000 cyc of gathers.
// Gather loop runs batches of 8 independent LDG.128 (32 L2 sectors in flight
// per warp). __launch_bounds__(256, 3) gives ptxas up to 85 regs so the 8-wide
// batch is actually register-allocated (R3 failed at 35 regs). Chunks padded
// with (v=0, c=0): dummy gathers hit the L1-hot col-0 row.
// ---------------------------------------------------------------------------
__global__ void __launch_bounds__(32 * WARPS_PER_BLOCK, 3)
spmm_kernel(const float* __restrict__ values,
            const float* __restrict__ w,
            const int*   __restrict__ cols32,
            float*       __restrict__ out) {
    const int warp = threadIdx.x >> 5;
    const int lane = threadIdx.x & 31;
    const int r    = blockIdx.x * WARPS_PER_BLOCK + warp;
    const int is64 = g_is64;

    __shared__ float sval[2][WARPS_PER_BLOCK][32];
    __shared__ int   scol[2][WARPS_PER_BLOCK][32];

    const int lo = g_row_start[r];
    const int hi = g_row_start[r + 1];

    float4 acc0 = make_float4(0.f, 0.f, 0.f, 0.f);
    float4 acc1 = make_float4(0.f, 0.f, 0.f, 0.f);
    const float4* __restrict__ w4 = (const float4*)w;   // w4[c*32 + lane]

    // Prime chunk 0 into buffer 0
    {
        float v = 0.0f; int c = 0;
        const int k = lo + lane;
        if (k < hi) {
            v = values[k];
            c = is64 ? cols32[2 * k] : cols32[k];
        }
        sval[0][warp][lane] = v;
        scol[0][warp][lane] = c;
    }
    __syncwarp();

    int buf = 0;
    #pragma unroll 1
    for (int base = lo; base < hi; base += 32) {
        // Prefetch next chunk into registers (overlaps the gather loop)
        float vn = 0.0f; int cn = 0;
        {
            const int kn = base + 32 + lane;
            if (kn < hi) {
                vn = values[kn];
                cn = is64 ? cols32[2 * kn] : cols32[kn];
            }
        }

        // Gather + accumulate: 4 batches of 8 independent LDG.128
        #pragma unroll 1
        for (int j = 0; j < 32; j += 8) {
            int c[8];
            #pragma unroll
            for (int jj = 0; jj < 8; jj++) c[jj] = scol[buf][warp][j + jj];

            float4 wv[8];
            #pragma unroll
            for (int jj = 0; jj < 8; jj++)
                wv[jj] = w4[(size_t)c[jj] * 32 + lane];

            #pragma unroll
            for (int jj = 0; jj < 8; jj += 2) {
                const float va = sval[buf][warp][j + jj];
                const float vb = sval[buf][warp][j + jj + 1];
                acc0.x = fmaf(va, wv[jj].x, acc0.x);
                acc0.y = fmaf(va, wv[jj].y, acc0.y);
                acc0.z = fmaf(va, wv[jj].z, acc0.z);
                acc0.w = fmaf(va, wv[jj].w, acc0.w);
                acc1.x = fmaf(vb, wv[jj + 1].x, acc1.x);
                acc1.y = fmaf(vb, wv[jj + 1].y, acc1.y);
                acc1.z = fmaf(vb, wv[jj + 1].z, acc1.z);
                acc1.w = fmaf(vb, wv[jj + 1].w, acc1.w);
            }
        }

        // Publish prefetched chunk to the alternate buffer
        sval[buf ^ 1][warp][lane] = vn;
        scol[buf ^ 1][warp][lane] = cn;
        __syncwarp();
        buf ^= 1;
    }

    acc0.x += acc1.x; acc0.y += acc1.y; acc0.z += acc1.z; acc0.w += acc1.w;
    ((float4*)out)[(size_t)r * 32 + lane] = acc0;
}

// ---------------------------------------------------------------------------
// Launch
// Inputs (metadata order): values f32[NNZ], w f32[8192*128],
//                          rows int{32,64}[NNZ], cols int{32,64}[NNZ], n_rows
// ---------------------------------------------------------------------------
extern "C" void kernel_launch(void* const* d_in, const int* in_sizes, int n_in,
                              void* d_out, int out_size) {
    const float* values = (const float*)d_in[0];
    const float* w      = (const float*)d_in[1];
    const int*   rows32 = (const int*)d_in[2];
    const int*   cols32 = (const int*)d_in[3];
    float*       out    = (float*)d_out;

    const int nnz    = in_sizes[0];
    const int n_rows = out_size / OUT_UNITS;

    const int bs = 256;
    const int nthreads = (nnz + 3) / 4;
    build_offsets_kernel<<<(nthreads + bs - 1) / bs, bs>>>(rows32, nnz, n_rows);

    spmm_kernel<<<n_rows / WARPS_PER_BLOCK, 32 * WARPS_PER_BLOCK>>>(values, w, cols32, out);
}